// round 2
// baseline (speedup 1.0000x reference)
#include <cuda_runtime.h>
#include <cuda_bf16.h>
#include <math.h>

// ---------------- problem constants ----------------
#define NN 50000
#define EE 800000
#define F_IN 512
#define H1 8
#define F_HID 8
#define O1 64          // H1*F_HID
#define NLAB 64
#define LRELU 0.2f

// ---------------- device scratch (no allocs allowed) ----------------
__device__ float g_Wt[F_IN * O1];          // W1 transposed to [k][o]
__device__ float g_Wh1[(size_t)NN * O1];   // layer-1 node features
__device__ float g_es1[NN * H1];
__device__ float g_ed1[NN * H1];
__device__ float g_h1[(size_t)NN * O1];    // post-aggregation, post-ELU
__device__ float g_Wh2[(size_t)NN * NLAB];
__device__ float g_es2[NN];
__device__ float g_ed2[NN];
__device__ int   g_cnt[NN];
__device__ int   g_cur[NN];
__device__ int   g_off[NN + 1];
__device__ int   g_ssrc[EE];

// ---------------- f32x2 helpers ----------------
__device__ __forceinline__ unsigned long long pack2(float lo, float hi) {
    unsigned long long r;
    asm("mov.b64 %0, {%1, %2};" : "=l"(r) : "f"(lo), "f"(hi));
    return r;
}
__device__ __forceinline__ void fma2(unsigned long long& acc, unsigned long long a,
                                     unsigned long long b) {
    asm("fma.rn.f32x2 %0, %1, %2, %0;" : "+l"(acc) : "l"(a), "l"(b));
}
__device__ __forceinline__ float2 unpack2(unsigned long long v) {
    float lo, hi;
    asm("mov.b64 {%0, %1}, %2;" : "=f"(lo), "=f"(hi) : "l"(v));
    return make_float2(lo, hi);
}

__device__ __forceinline__ float lrelu_f(float v) { return v > 0.f ? v : LRELU * v; }
__device__ __forceinline__ float elu_f(float v)   { return v > 0.f ? v : __expf(v) - 1.f; }

// ---------------- prep: transpose W1 to [k][o64], zero counters ----------------
__global__ void prep_kernel(const float* __restrict__ W1) {
    int i = blockIdx.x * blockDim.x + threadIdx.x;
    if (i < F_IN * O1) {
        int k = i >> 6, o = i & 63;
        // W1: [H1, F_IN, F_HID] -> flat h*4096 + k*8 + of
        g_Wt[i] = W1[(o >> 3) * (F_IN * F_HID) + k * F_HID + (o & 7)];
    }
    if (i < NN) g_cnt[i] = 0;
}

// ---------------- GEMM1: Wh1 = x @ Wt, es1/ed1 epilogue ----------------
// block = 256 thr (8 warps), 8 nodes/warp -> 64 nodes/block. K staged in smem
// chunks of 128. Lane owns outputs (2l, 2l+1); k-pairs packed into f32x2.
#define G1_NB 64
#define G1_KC 128
__global__ __launch_bounds__(256) void gemm1_kernel(const float* __restrict__ x,
                                                    const float* __restrict__ a1s,
                                                    const float* __restrict__ a1d) {
    __shared__ float xs[G1_NB][G1_KC];
    const int tid = threadIdx.x;
    const int lane = tid & 31;
    const int w = tid >> 5;
    const int nb0 = blockIdx.x * G1_NB;

    unsigned long long acc[8][2];
#pragma unroll
    for (int n = 0; n < 8; n++) { acc[n][0] = 0ull; acc[n][1] = 0ull; }

    const float2* Wt2 = (const float2*)g_Wt;

    for (int kt = 0; kt < F_IN; kt += G1_KC) {
        __syncthreads();
        // cooperative stage of x[nb0 .. nb0+63][kt .. kt+127]
        for (int idx = tid; idx < G1_NB * (G1_KC / 4); idx += 256) {
            int n = idx / (G1_KC / 4);
            int c = idx % (G1_KC / 4);
            int g = nb0 + n;
            float4 v = make_float4(0.f, 0.f, 0.f, 0.f);
            if (g < NN) v = *(const float4*)&x[(size_t)g * F_IN + kt + c * 4];
            *(float4*)&xs[n][c * 4] = v;
        }
        __syncthreads();

        const int nrow = w * 8;
#pragma unroll 4
        for (int k = 0; k < G1_KC; k += 2) {
            float2 wa = __ldg(&Wt2[(kt + k) * 32 + lane]);
            float2 wb = __ldg(&Wt2[(kt + k + 1) * 32 + lane]);
            unsigned long long t0 = pack2(wa.x, wb.x);
            unsigned long long t1 = pack2(wa.y, wb.y);
#pragma unroll
            for (int n = 0; n < 8; n++) {
                unsigned long long xv = *(const unsigned long long*)&xs[nrow + n][k];
                fma2(acc[n][0], xv, t0);
                fma2(acc[n][1], xv, t1);
            }
        }
    }

    const float as0 = a1s[2 * lane], as1 = a1s[2 * lane + 1];
    const float ad0 = a1d[2 * lane], ad1 = a1d[2 * lane + 1];
#pragma unroll
    for (int n = 0; n < 8; n++) {
        int g = nb0 + w * 8 + n;
        if (g >= NN) continue;  // uniform across warp
        float2 p0 = unpack2(acc[n][0]);
        float2 p1 = unpack2(acc[n][1]);
        float o0 = p0.x + p0.y;
        float o1 = p1.x + p1.y;
        *(float2*)&g_Wh1[(size_t)g * O1 + 2 * lane] = make_float2(o0, o1);
        float ps = o0 * as0 + o1 * as1;
        float pd = o0 * ad0 + o1 * ad1;
        ps += __shfl_xor_sync(0xffffffffu, ps, 1);
        ps += __shfl_xor_sync(0xffffffffu, ps, 2);
        pd += __shfl_xor_sync(0xffffffffu, pd, 1);
        pd += __shfl_xor_sync(0xffffffffu, pd, 2);
        if ((lane & 3) == 0) {
            g_es1[g * H1 + (lane >> 2)] = ps;
            g_ed1[g * H1 + (lane >> 2)] = pd;
        }
    }
}

// ---------------- counting sort by dst ----------------
__global__ void hist_kernel(const int* __restrict__ dst) {
    int e = blockIdx.x * blockDim.x + threadIdx.x;
    if (e < EE) atomicAdd(&g_cnt[dst[e]], 1);
}

__global__ __launch_bounds__(1024) void scan_kernel() {
    __shared__ int ssum[1024];
    const int t = threadIdx.x;
    const int CH = (NN + 1023) / 1024;
    int b = t * CH;
    int e2 = b + CH; if (e2 > NN) e2 = NN;
    int s = 0;
    for (int i = b; i < e2; i++) s += g_cnt[i];
    ssum[t] = s;
    __syncthreads();
    for (int d = 1; d < 1024; d <<= 1) {
        int v = (t >= d) ? ssum[t - d] : 0;
        __syncthreads();
        ssum[t] += v;
        __syncthreads();
    }
    int off = (t == 0) ? 0 : ssum[t - 1];
    for (int i = b; i < e2; i++) {
        g_off[i] = off;
        g_cur[i] = off;
        off += g_cnt[i];
    }
    if (t == 1023) g_off[NN] = ssum[1023];
}

__global__ void scatter_kernel(const int* __restrict__ src, const int* __restrict__ dst) {
    int e = blockIdx.x * blockDim.x + threadIdx.x;
    if (e < EE) {
        int d = dst[e];
        int p = atomicAdd(&g_cur[d], 1);
        g_ssrc[p] = src[e];
    }
}

// ---------------- layer-1 edge softmax + aggregation (warp per dst node) ----------------
__global__ __launch_bounds__(256) void agg1_kernel() {
    int node = (blockIdx.x * blockDim.x + threadIdx.x) >> 5;
    int lane = threadIdx.x & 31;
    if (node >= NN) return;
    const int beg = g_off[node], end = g_off[node + 1];

    float ed[8];
    {
        float4 a = *(const float4*)&g_ed1[node * H1];
        float4 b = *(const float4*)&g_ed1[node * H1 + 4];
        ed[0] = a.x; ed[1] = a.y; ed[2] = a.z; ed[3] = a.w;
        ed[4] = b.x; ed[5] = b.y; ed[6] = b.z; ed[7] = b.w;
    }

    float mx[8];
#pragma unroll
    for (int h = 0; h < 8; h++) mx[h] = -3.0e38f;
    for (int i = beg + lane; i < end; i += 32) {
        int s = g_ssrc[i];
        float4 a = *(const float4*)&g_es1[s * H1];
        float4 b = *(const float4*)&g_es1[s * H1 + 4];
        float ev[8] = {a.x, a.y, a.z, a.w, b.x, b.y, b.z, b.w};
#pragma unroll
        for (int h = 0; h < 8; h++) mx[h] = fmaxf(mx[h], lrelu_f(ev[h] + ed[h]));
    }
#pragma unroll
    for (int h = 0; h < 8; h++)
        for (int o = 16; o; o >>= 1)
            mx[h] = fmaxf(mx[h], __shfl_xor_sync(0xffffffffu, mx[h], o));

    float sm[8];
#pragma unroll
    for (int h = 0; h < 8; h++) sm[h] = 0.f;
    for (int i = beg + lane; i < end; i += 32) {
        int s = g_ssrc[i];
        float4 a = *(const float4*)&g_es1[s * H1];
        float4 b = *(const float4*)&g_es1[s * H1 + 4];
        float ev[8] = {a.x, a.y, a.z, a.w, b.x, b.y, b.z, b.w};
#pragma unroll
        for (int h = 0; h < 8; h++) sm[h] += __expf(lrelu_f(ev[h] + ed[h]) - mx[h]);
    }
#pragma unroll
    for (int h = 0; h < 8; h++)
        for (int o = 16; o; o >>= 1)
            sm[h] += __shfl_xor_sync(0xffffffffu, sm[h], o);

    const int h = lane >> 2;
    const float mh = mx[h];
    const float invh = 1.f / (sm[h] + 1e-10f);
    const float edh = ed[h];

    float2 acc = make_float2(0.f, 0.f);
    for (int i = beg; i < end; i++) {
        int s = g_ssrc[i];  // warp-uniform
        float e = lrelu_f(g_es1[s * H1 + h] + edh);
        float a = __expf(e - mh) * invh;
        float2 w2 = *(const float2*)&g_Wh1[(size_t)s * O1 + 2 * lane];
        acc.x += a * w2.x;
        acc.y += a * w2.y;
    }
    // concat heads + ELU
    *(float2*)&g_h1[(size_t)node * O1 + 2 * lane] =
        make_float2(elu_f(acc.x), elu_f(acc.y));
}

// ---------------- GEMM2: Wh2 = h1 @ W2, es2/ed2 epilogue (warp per node) ----------------
__global__ __launch_bounds__(256) void gemm2_kernel(const float* __restrict__ W2,
                                                    const float* __restrict__ a2s,
                                                    const float* __restrict__ a2d) {
    int node = (blockIdx.x * blockDim.x + threadIdx.x) >> 5;
    int lane = threadIdx.x & 31;
    if (node >= NN) return;
    float2 hv = *(const float2*)&g_h1[(size_t)node * O1 + 2 * lane];
    const float2* W2f2 = (const float2*)W2;
    float2 acc = make_float2(0.f, 0.f);
#pragma unroll
    for (int k = 0; k < O1; k++) {
        float xk = __shfl_sync(0xffffffffu, (k & 1) ? hv.y : hv.x, k >> 1);
        float2 w = __ldg(&W2f2[k * 32 + lane]);
        acc.x += xk * w.x;
        acc.y += xk * w.y;
    }
    *(float2*)&g_Wh2[(size_t)node * NLAB + 2 * lane] = acc;
    float ps = acc.x * a2s[2 * lane] + acc.y * a2s[2 * lane + 1];
    float pd = acc.x * a2d[2 * lane] + acc.y * a2d[2 * lane + 1];
#pragma unroll
    for (int o = 16; o; o >>= 1) {
        ps += __shfl_xor_sync(0xffffffffu, ps, o);
        pd += __shfl_xor_sync(0xffffffffu, pd, o);
    }
    if (lane == 0) { g_es2[node] = ps; g_ed2[node] = pd; }
}

// ---------------- layer-2 aggregation + fused final softmax ----------------
__global__ __launch_bounds__(256) void agg2_kernel(float* __restrict__ out) {
    int node = (blockIdx.x * blockDim.x + threadIdx.x) >> 5;
    int lane = threadIdx.x & 31;
    if (node >= NN) return;
    const int beg = g_off[node], end = g_off[node + 1];
    const float ed = g_ed2[node];

    float mx = -3.0e38f;
    for (int i = beg + lane; i < end; i += 32)
        mx = fmaxf(mx, lrelu_f(g_es2[g_ssrc[i]] + ed));
#pragma unroll
    for (int o = 16; o; o >>= 1) mx = fmaxf(mx, __shfl_xor_sync(0xffffffffu, mx, o));

    float sm = 0.f;
    for (int i = beg + lane; i < end; i += 32)
        sm += __expf(lrelu_f(g_es2[g_ssrc[i]] + ed) - mx);
#pragma unroll
    for (int o = 16; o; o >>= 1) sm += __shfl_xor_sync(0xffffffffu, sm, o);
    const float inv = 1.f / (sm + 1e-10f);

    float2 acc = make_float2(0.f, 0.f);
    for (int i = beg; i < end; i++) {
        int s = g_ssrc[i];  // warp-uniform
        float a = __expf(lrelu_f(g_es2[s] + ed) - mx) * inv;
        float2 w2 = *(const float2*)&g_Wh2[(size_t)s * NLAB + 2 * lane];
        acc.x += a * w2.x;
        acc.y += a * w2.y;
    }
    // head-mean is identity (H2=1); fused softmax over 64 classes
    float m2 = fmaxf(acc.x, acc.y);
#pragma unroll
    for (int o = 16; o; o >>= 1) m2 = fmaxf(m2, __shfl_xor_sync(0xffffffffu, m2, o));
    float e0 = __expf(acc.x - m2);
    float e1 = __expf(acc.y - m2);
    float s2 = e0 + e1;
#pragma unroll
    for (int o = 16; o; o >>= 1) s2 += __shfl_xor_sync(0xffffffffu, s2, o);
    float r = 1.f / s2;
    *(float2*)&out[(size_t)node * NLAB + 2 * lane] = make_float2(e0 * r, e1 * r);
}

// ---------------- launch ----------------
extern "C" void kernel_launch(void* const* d_in, const int* in_sizes, int n_in,
                              void* d_out, int out_size) {
    const float* x    = (const float*)d_in[0];
    const float* W1   = (const float*)d_in[1];
    const float* a1s  = (const float*)d_in[2];
    const float* a1d  = (const float*)d_in[3];
    const float* W2   = (const float*)d_in[4];
    const float* a2s  = (const float*)d_in[5];
    const float* a2d  = (const float*)d_in[6];
    const int*   src  = (const int*)d_in[7];
    const int*   dst  = (const int*)d_in[8];
    float* out = (float*)d_out;

    prep_kernel<<<(NN + 255) / 256, 256>>>(W1);
    hist_kernel<<<(EE + 255) / 256, 256>>>(dst);
    scan_kernel<<<1, 1024>>>();
    scatter_kernel<<<(EE + 255) / 256, 256>>>(src, dst);
    gemm1_kernel<<<(NN + G1_NB - 1) / G1_NB, 256>>>(x, a1s, a1d);
    agg1_kernel<<<(NN * 32 + 255) / 256, 256>>>();
    gemm2_kernel<<<(NN * 32 + 255) / 256, 256>>>(W2, a2s, a2d);
    agg2_kernel<<<(NN * 32 + 255) / 256, 256>>>(out);
}

// round 3
// speedup vs baseline: 1.1764x; 1.1764x over previous
#include <cuda_runtime.h>
#include <cuda_bf16.h>
#include <math.h>

// ---------------- problem constants ----------------
#define NN 50000
#define EE 800000
#define F_IN 512
#define H1 8
#define F_HID 8
#define O1 64          // H1*F_HID
#define NLAB 64
#define LRELU 0.2f

// ---------------- device scratch (no allocs allowed) ----------------
__device__ ulonglong2 g_Wp[(F_IN / 2) * 32];   // W1 packed: [kpair][lane] -> {(o=2l),(o=2l+1)} f32x2
__device__ float g_Wh1[(size_t)NN * O1];       // layer-1 node features
__device__ float g_es1[NN * H1];
__device__ float g_ed1[NN * H1];
__device__ float g_h1[(size_t)NN * O1];        // post-aggregation, post-ELU
__device__ float g_Wh2[(size_t)NN * NLAB];
__device__ float g_es2[NN];
__device__ float g_ed2[NN];
__device__ int   g_cnt[NN];
__device__ int   g_cur[NN];
__device__ int   g_off[NN + 1];
__device__ int   g_ssrc[EE];

// ---------------- f32x2 helpers ----------------
__device__ __forceinline__ unsigned long long pack2(float lo, float hi) {
    unsigned long long r;
    asm("mov.b64 %0, {%1, %2};" : "=l"(r) : "f"(lo), "f"(hi));
    return r;
}
__device__ __forceinline__ void fma2(unsigned long long& acc, unsigned long long a,
                                     unsigned long long b) {
    asm("fma.rn.f32x2 %0, %1, %2, %0;" : "+l"(acc) : "l"(a), "l"(b));
}
__device__ __forceinline__ float2 unpack2(unsigned long long v) {
    float lo, hi;
    asm("mov.b64 {%0, %1}, %2;" : "=f"(lo), "=f"(hi) : "l"(v));
    return make_float2(lo, hi);
}

__device__ __forceinline__ float lrelu_f(float v) { return fmaxf(v, LRELU * v); }
__device__ __forceinline__ float elu_f(float v)   { return v > 0.f ? v : __expf(v) - 1.f; }

// ---------------- prep: pack W1 for f32x2, zero counters ----------------
__global__ void prep_kernel(const float* __restrict__ W1) {
    int i = blockIdx.x * blockDim.x + threadIdx.x;
    if (i < (F_IN / 2) * 32) {
        int p = i >> 5, l = i & 31;
        int o0 = 2 * l, o1 = 2 * l + 1;
        int k0 = 2 * p, k1 = 2 * p + 1;
        // W1: [H1, F_IN, F_HID]; element (k,o) at (o>>3)*4096 + k*8 + (o&7)
        float w00 = W1[(o0 >> 3) * (F_IN * F_HID) + k0 * F_HID + (o0 & 7)];
        float w10 = W1[(o0 >> 3) * (F_IN * F_HID) + k1 * F_HID + (o0 & 7)];
        float w01 = W1[(o1 >> 3) * (F_IN * F_HID) + k0 * F_HID + (o1 & 7)];
        float w11 = W1[(o1 >> 3) * (F_IN * F_HID) + k1 * F_HID + (o1 & 7)];
        ulonglong2 v;
        v.x = pack2(w00, w10);
        v.y = pack2(w01, w11);
        g_Wp[i] = v;
    }
    if (i < NN) g_cnt[i] = 0;
}

// ---------------- GEMM1: Wh1 = x @ W1, es1/ed1 epilogue ----------------
// 256 thr (8 warps), 8 nodes/warp -> 64 nodes/block. Lane owns outputs (2l,2l+1).
// f32x2 lanes act as a 2-way K split (lo=even k, hi=odd k); summed in epilogue.
#define G1_NB 64
#define G1_KC 128
__global__ __launch_bounds__(256) void gemm1_kernel(const float* __restrict__ x,
                                                    const float* __restrict__ a1s,
                                                    const float* __restrict__ a1d) {
    __shared__ float xs[G1_NB][G1_KC];
    const int tid = threadIdx.x;
    const int lane = tid & 31;
    const int w = tid >> 5;
    const int nb0 = blockIdx.x * G1_NB;

    unsigned long long acc[8][2];
#pragma unroll
    for (int n = 0; n < 8; n++) { acc[n][0] = 0ull; acc[n][1] = 0ull; }

    for (int kt = 0; kt < F_IN; kt += G1_KC) {
        __syncthreads();
        for (int idx = tid; idx < G1_NB * (G1_KC / 4); idx += 256) {
            int n = idx / (G1_KC / 4);
            int c = idx % (G1_KC / 4);
            int g = nb0 + n;
            float4 v = make_float4(0.f, 0.f, 0.f, 0.f);
            if (g < NN) v = *(const float4*)&x[(size_t)g * F_IN + kt + c * 4];
            *(float4*)&xs[n][c * 4] = v;
        }
        __syncthreads();

        const int nrow = w * 8;
        const int pbase = kt >> 1;
#pragma unroll 4
        for (int q = 0; q < G1_KC / 2; q += 2) {
            ulonglong2 wA = g_Wp[(pbase + q) * 32 + lane];
            ulonglong2 wB = g_Wp[(pbase + q + 1) * 32 + lane];
#pragma unroll
            for (int n = 0; n < 8; n++) {
                ulonglong2 xv = *(const ulonglong2*)&xs[nrow + n][2 * q];
                fma2(acc[n][0], xv.x, wA.x);
                fma2(acc[n][1], xv.x, wA.y);
                fma2(acc[n][0], xv.y, wB.x);
                fma2(acc[n][1], xv.y, wB.y);
            }
        }
    }

    const float as0 = a1s[2 * lane], as1 = a1s[2 * lane + 1];
    const float ad0 = a1d[2 * lane], ad1 = a1d[2 * lane + 1];
#pragma unroll
    for (int n = 0; n < 8; n++) {
        int g = nb0 + w * 8 + n;
        if (g >= NN) continue;  // uniform across warp
        float2 p0 = unpack2(acc[n][0]);
        float2 p1 = unpack2(acc[n][1]);
        float o0 = p0.x + p0.y;
        float o1 = p1.x + p1.y;
        *(float2*)&g_Wh1[(size_t)g * O1 + 2 * lane] = make_float2(o0, o1);
        float ps = o0 * as0 + o1 * as1;
        float pd = o0 * ad0 + o1 * ad1;
        ps += __shfl_xor_sync(0xffffffffu, ps, 1);
        ps += __shfl_xor_sync(0xffffffffu, ps, 2);
        pd += __shfl_xor_sync(0xffffffffu, pd, 1);
        pd += __shfl_xor_sync(0xffffffffu, pd, 2);
        if ((lane & 3) == 0) {
            g_es1[g * H1 + (lane >> 2)] = ps;
            g_ed1[g * H1 + (lane >> 2)] = pd;
        }
    }
}

// ---------------- counting sort by dst ----------------
__global__ void hist_kernel(const int* __restrict__ dst) {
    int e = blockIdx.x * blockDim.x + threadIdx.x;
    if (e < EE) atomicAdd(&g_cnt[dst[e]], 1);
}

__global__ __launch_bounds__(1024) void scan_kernel() {
    __shared__ int ssum[1024];
    const int t = threadIdx.x;
    const int CH = (NN + 1023) / 1024;
    int b = t * CH;
    int e2 = b + CH; if (e2 > NN) e2 = NN;
    int s = 0;
    for (int i = b; i < e2; i++) s += g_cnt[i];
    ssum[t] = s;
    __syncthreads();
    for (int d = 1; d < 1024; d <<= 1) {
        int v = (t >= d) ? ssum[t - d] : 0;
        __syncthreads();
        ssum[t] += v;
        __syncthreads();
    }
    int off = (t == 0) ? 0 : ssum[t - 1];
    for (int i = b; i < e2; i++) {
        g_off[i] = off;
        g_cur[i] = off;
        off += g_cnt[i];
    }
    if (t == 1023) g_off[NN] = ssum[1023];
}

__global__ void scatter_kernel(const int* __restrict__ src, const int* __restrict__ dst) {
    int e = blockIdx.x * blockDim.x + threadIdx.x;
    if (e < EE) {
        int d = dst[e];
        int p = atomicAdd(&g_cur[d], 1);
        g_ssrc[p] = src[e];
    }
}

// ---------------- layer-1 softmax-aggregate, SINGLE pass (warp per dst node) ----
// softmax max-shift is unnecessary (bounded logits) and cancels in normalization.
__global__ __launch_bounds__(256) void agg1_kernel() {
    int node = (blockIdx.x * blockDim.x + threadIdx.x) >> 5;
    int lane = threadIdx.x & 31;
    if (node >= NN) return;
    const int beg = g_off[node], end = g_off[node + 1];
    const int h = lane >> 2;
    const float edh = g_ed1[node * H1 + h];

    float sumP = 0.f;
    float2 acc = make_float2(0.f, 0.f);
    for (int i = beg; i < end; i++) {
        int s = g_ssrc[i];  // warp-uniform
        float e = lrelu_f(g_es1[s * H1 + h] + edh);
        float p = __expf(e);
        sumP += p;
        float2 w2 = *(const float2*)&g_Wh1[(size_t)s * O1 + 2 * lane];
        acc.x += p * w2.x;
        acc.y += p * w2.y;
    }
    const float inv = 1.f / (sumP + 1e-10f);
    *(float2*)&g_h1[(size_t)node * O1 + 2 * lane] =
        make_float2(elu_f(acc.x * inv), elu_f(acc.y * inv));
}

// ---------------- GEMM2: Wh2 = h1 @ W2, es2/ed2 epilogue (warp per node) ----------------
__global__ __launch_bounds__(256) void gemm2_kernel(const float* __restrict__ W2,
                                                    const float* __restrict__ a2s,
                                                    const float* __restrict__ a2d) {
    int node = (blockIdx.x * blockDim.x + threadIdx.x) >> 5;
    int lane = threadIdx.x & 31;
    if (node >= NN) return;
    float2 hv = *(const float2*)&g_h1[(size_t)node * O1 + 2 * lane];
    const float2* W2f2 = (const float2*)W2;
    float2 acc = make_float2(0.f, 0.f);
#pragma unroll
    for (int k = 0; k < O1; k++) {
        float xk = __shfl_sync(0xffffffffu, (k & 1) ? hv.y : hv.x, k >> 1);
        float2 w = __ldg(&W2f2[k * 32 + lane]);
        acc.x += xk * w.x;
        acc.y += xk * w.y;
    }
    *(float2*)&g_Wh2[(size_t)node * NLAB + 2 * lane] = acc;
    float ps = acc.x * a2s[2 * lane] + acc.y * a2s[2 * lane + 1];
    float pd = acc.x * a2d[2 * lane] + acc.y * a2d[2 * lane + 1];
#pragma unroll
    for (int o = 16; o; o >>= 1) {
        ps += __shfl_xor_sync(0xffffffffu, ps, o);
        pd += __shfl_xor_sync(0xffffffffu, pd, o);
    }
    if (lane == 0) { g_es2[node] = ps; g_ed2[node] = pd; }
}

// ---------------- layer-2 aggregate (single pass) + fused final softmax ----------------
__global__ __launch_bounds__(256) void agg2_kernel(float* __restrict__ out) {
    int node = (blockIdx.x * blockDim.x + threadIdx.x) >> 5;
    int lane = threadIdx.x & 31;
    if (node >= NN) return;
    const int beg = g_off[node], end = g_off[node + 1];
    const float ed = g_ed2[node];

    float sumP = 0.f;
    float2 acc = make_float2(0.f, 0.f);
    for (int i = beg; i < end; i++) {
        int s = g_ssrc[i];  // warp-uniform
        float p = __expf(lrelu_f(g_es2[s] + ed));
        sumP += p;
        float2 w2 = *(const float2*)&g_Wh2[(size_t)s * NLAB + 2 * lane];
        acc.x += p * w2.x;
        acc.y += p * w2.y;
    }
    const float inv = 1.f / (sumP + 1e-10f);
    float o0 = acc.x * inv;
    float o1 = acc.y * inv;

    // head-mean is identity (H2=1); fused softmax over 64 classes
    float m2 = fmaxf(o0, o1);
#pragma unroll
    for (int o = 16; o; o >>= 1) m2 = fmaxf(m2, __shfl_xor_sync(0xffffffffu, m2, o));
    float e0 = __expf(o0 - m2);
    float e1 = __expf(o1 - m2);
    float s2 = e0 + e1;
#pragma unroll
    for (int o = 16; o; o >>= 1) s2 += __shfl_xor_sync(0xffffffffu, s2, o);
    float r = 1.f / s2;
    *(float2*)&out[(size_t)node * NLAB + 2 * lane] = make_float2(e0 * r, e1 * r);
}

// ---------------- launch ----------------
extern "C" void kernel_launch(void* const* d_in, const int* in_sizes, int n_in,
                              void* d_out, int out_size) {
    const float* x    = (const float*)d_in[0];
    const float* W1   = (const float*)d_in[1];
    const float* a1s  = (const float*)d_in[2];
    const float* a1d  = (const float*)d_in[3];
    const float* W2   = (const float*)d_in[4];
    const float* a2s  = (const float*)d_in[5];
    const float* a2d  = (const float*)d_in[6];
    const int*   src  = (const int*)d_in[7];
    const int*   dst  = (const int*)d_in[8];
    float* out = (float*)d_out;

    prep_kernel<<<(NN + 255) / 256, 256>>>(W1);
    hist_kernel<<<(EE + 255) / 256, 256>>>(dst);
    scan_kernel<<<1, 1024>>>();
    scatter_kernel<<<(EE + 255) / 256, 256>>>(src, dst);
    gemm1_kernel<<<(NN + G1_NB - 1) / G1_NB, 256>>>(x, a1s, a1d);
    agg1_kernel<<<(NN * 32 + 255) / 256, 256>>>();
    gemm2_kernel<<<(NN * 32 + 255) / 256, 256>>>(W2, a2s, a2d);
    agg2_kernel<<<(NN * 32 + 255) / 256, 256>>>(out);
}

// round 4
// speedup vs baseline: 1.4705x; 1.2500x over previous
#include <cuda_runtime.h>
#include <cuda_bf16.h>
#include <math.h>

// ---------------- problem constants ----------------
#define NN 50000
#define EE 800000
#define F_IN 512
#define H1 8
#define F_HID 8
#define O1 64          // H1*F_HID
#define NLAB 64
#define LRELU 0.2f

#define FULLM 0xffffffffu

// ---------------- device scratch (no allocs allowed) ----------------
__device__ ulonglong2 g_Wp[(F_IN / 2) * 32];   // W1 packed: [kpair][lane] -> {(o=2l),(o=2l+1)} f32x2
__device__ float g_Wh1[(size_t)NN * O1];       // layer-1 node features
__device__ float g_es1[NN * H1];
__device__ float g_ed1[NN * H1];
__device__ float g_Wh2[(size_t)NN * NLAB];
__device__ float g_es2[NN];
__device__ float g_ed2[NN];
__device__ int   g_cnt[NN];                    // zero at entry of every call (re-zeroed at tail)
__device__ int   g_rank[EE];
__device__ int   g_off[NN + 1];
__device__ int   g_ssrc[EE];

// ---------------- f32x2 helpers ----------------
__device__ __forceinline__ unsigned long long pack2(float lo, float hi) {
    unsigned long long r;
    asm("mov.b64 %0, {%1, %2};" : "=l"(r) : "f"(lo), "f"(hi));
    return r;
}
__device__ __forceinline__ void fma2(unsigned long long& acc, unsigned long long a,
                                     unsigned long long b) {
    asm("fma.rn.f32x2 %0, %1, %2, %0;" : "+l"(acc) : "l"(a), "l"(b));
}
__device__ __forceinline__ float2 unpack2(unsigned long long v) {
    float lo, hi;
    asm("mov.b64 {%0, %1}, %2;" : "=f"(lo), "=f"(hi) : "l"(v));
    return make_float2(lo, hi);
}

__device__ __forceinline__ float lrelu_f(float v) { return fmaxf(v, LRELU * v); }
__device__ __forceinline__ float elu_f(float v)   { return v > 0.f ? v : __expf(v) - 1.f; }

// ================= K1: prep (pack W1) + hist (rank-storing) =================
// blocks [0,32): pack W1.  blocks [32, 32+3125): histogram with rank capture.
#define HIST_BLKS ((EE + 255) / 256)
__global__ __launch_bounds__(256) void k1_prep_hist(const float* __restrict__ W1,
                                                    const int* __restrict__ dst) {
    const int bid = blockIdx.x;
    const int tid = threadIdx.x;
    if (bid < 32) {
        int i = bid * 256 + tid;   // < 8192 = (F_IN/2)*32
        int p = i >> 5, l = i & 31;
        int o0 = 2 * l, o1 = 2 * l + 1;
        int k0 = 2 * p, k1 = 2 * p + 1;
        // W1: [H1, F_IN, F_HID]; element (k,o) at (o>>3)*4096 + k*8 + (o&7)
        float w00 = W1[(o0 >> 3) * (F_IN * F_HID) + k0 * F_HID + (o0 & 7)];
        float w10 = W1[(o0 >> 3) * (F_IN * F_HID) + k1 * F_HID + (o0 & 7)];
        float w01 = W1[(o1 >> 3) * (F_IN * F_HID) + k0 * F_HID + (o1 & 7)];
        float w11 = W1[(o1 >> 3) * (F_IN * F_HID) + k1 * F_HID + (o1 & 7)];
        ulonglong2 v;
        v.x = pack2(w00, w10);
        v.y = pack2(w01, w11);
        g_Wp[i] = v;
    } else {
        int e = (bid - 32) * 256 + tid;
        if (e < EE) g_rank[e] = atomicAdd(&g_cnt[dst[e]], 1);
    }
}

// ================= K2: gemm1 (blocks 1..) + scan (block 0) =================
#define G1_NB 64
#define G1_KC 128
__global__ __launch_bounds__(256) void k2_gemm1_scan(const float* __restrict__ x,
                                                     const float* __restrict__ a1s,
                                                     const float* __restrict__ a1d) {
    __shared__ float xs[G1_NB][G1_KC];   // 32KB (scan block reuses a corner)
    const int tid = threadIdx.x;

    if (blockIdx.x == 0) {
        // ---- exclusive scan of g_cnt -> g_off (256 threads) ----
        int* ssum = (int*)xs;
        const int CH = (NN + 255) / 256;   // 196
        int b = tid * CH;
        int e2 = b + CH; if (e2 > NN) e2 = NN;
        int s = 0;
        for (int i = b; i < e2; i++) s += g_cnt[i];
        ssum[tid] = s;
        __syncthreads();
        for (int d = 1; d < 256; d <<= 1) {
            int v = (tid >= d) ? ssum[tid - d] : 0;
            __syncthreads();
            ssum[tid] += v;
            __syncthreads();
        }
        int off = (tid == 0) ? 0 : ssum[tid - 1];
        for (int i = b; i < e2; i++) {
            g_off[i] = off;
            off += g_cnt[i];
        }
        if (tid == 255) g_off[NN] = ssum[255];
        return;
    }

    // ---- gemm1: Wh1 = x @ W1 (+ es1/ed1 epilogue), f32x2 ----
    const int lane = tid & 31;
    const int w = tid >> 5;
    const int nb0 = (blockIdx.x - 1) * G1_NB;

    unsigned long long acc[8][2];
#pragma unroll
    for (int n = 0; n < 8; n++) { acc[n][0] = 0ull; acc[n][1] = 0ull; }

    for (int kt = 0; kt < F_IN; kt += G1_KC) {
        __syncthreads();
        for (int idx = tid; idx < G1_NB * (G1_KC / 4); idx += 256) {
            int n = idx >> 5;          // /32
            int c = idx & 31;
            int g = nb0 + n;
            float4 v = make_float4(0.f, 0.f, 0.f, 0.f);
            if (g < NN) v = *(const float4*)&x[(size_t)g * F_IN + kt + c * 4];
            *(float4*)&xs[n][c * 4] = v;
        }
        __syncthreads();

        const int nrow = w * 8;
        const int pbase = kt >> 1;
#pragma unroll 4
        for (int q = 0; q < G1_KC / 2; q += 2) {
            ulonglong2 wA = g_Wp[(pbase + q) * 32 + lane];
            ulonglong2 wB = g_Wp[(pbase + q + 1) * 32 + lane];
#pragma unroll
            for (int n = 0; n < 8; n++) {
                ulonglong2 xv = *(const ulonglong2*)&xs[nrow + n][2 * q];
                fma2(acc[n][0], xv.x, wA.x);
                fma2(acc[n][1], xv.x, wA.y);
                fma2(acc[n][0], xv.y, wB.x);
                fma2(acc[n][1], xv.y, wB.y);
            }
        }
    }

    const float as0 = a1s[2 * lane], as1 = a1s[2 * lane + 1];
    const float ad0 = a1d[2 * lane], ad1 = a1d[2 * lane + 1];
#pragma unroll
    for (int n = 0; n < 8; n++) {
        int g = nb0 + w * 8 + n;
        if (g >= NN) continue;  // uniform across warp
        float2 p0 = unpack2(acc[n][0]);
        float2 p1 = unpack2(acc[n][1]);
        float o0 = p0.x + p0.y;
        float o1 = p1.x + p1.y;
        *(float2*)&g_Wh1[(size_t)g * O1 + 2 * lane] = make_float2(o0, o1);
        float ps = o0 * as0 + o1 * as1;
        float pd = o0 * ad0 + o1 * ad1;
        ps += __shfl_xor_sync(FULLM, ps, 1);
        ps += __shfl_xor_sync(FULLM, ps, 2);
        pd += __shfl_xor_sync(FULLM, pd, 1);
        pd += __shfl_xor_sync(FULLM, pd, 2);
        if ((lane & 3) == 0) {
            g_es1[g * H1 + (lane >> 2)] = ps;
            g_ed1[g * H1 + (lane >> 2)] = pd;
        }
    }
}

// ================= K3: scatter (atomic-free, rank-based) =================
__global__ void k3_scatter(const int* __restrict__ src, const int* __restrict__ dst) {
    int e = blockIdx.x * blockDim.x + threadIdx.x;
    if (e < EE) g_ssrc[g_off[dst[e]] + g_rank[e]] = src[e];
}

// ============ K4: layer-1 softmax-aggregate + ELU + GEMM2 fused ============
// warp per dst node; single edge pass (softmax max-shift cancels; logits bounded).
// h never leaves registers; W2 staged in smem per block.
__global__ __launch_bounds__(256) void k4_agg1_gemm2(const float* __restrict__ W2,
                                                     const float* __restrict__ a2s,
                                                     const float* __restrict__ a2d) {
    __shared__ unsigned long long sW2[O1 * 32];  // [k][lane] -> {W2[k][2l], W2[k][2l+1]} 16KB
    __shared__ float sa2s[NLAB], sa2d[NLAB];
    const int tid = threadIdx.x;
    const int lane = tid & 31;

    for (int idx = tid; idx < O1 * 32; idx += 256)
        sW2[idx] = *(const unsigned long long*)&W2[idx * 2];
    if (tid < NLAB) { sa2s[tid] = a2s[tid]; sa2d[tid] = a2d[tid]; }
    __syncthreads();

    int node = blockIdx.x * 8 + (tid >> 5);
    if (node >= NN) return;
    const int beg = g_off[node], end = g_off[node + 1];
    const int h = lane >> 2;
    const float edh = g_ed1[node * H1 + h];

    float sumP = 0.f;
    float2 acc = make_float2(0.f, 0.f);
    for (int base = beg; base < end; base += 32) {
        int rem = end - base;
        int s_l = (lane < rem) ? g_ssrc[base + lane] : 0;
        int m = rem < 32 ? rem : 32;
        for (int j = 0; j < m; j++) {
            int s = __shfl_sync(FULLM, s_l, j);
            float p = __expf(lrelu_f(g_es1[s * H1 + h] + edh));
            float2 w2 = *(const float2*)&g_Wh1[(size_t)s * O1 + 2 * lane];
            sumP += p;
            acc.x += p * w2.x;
            acc.y += p * w2.y;
        }
    }
    const float inv = 1.f / (sumP + 1e-10f);
    float2 hv = make_float2(elu_f(acc.x * inv), elu_f(acc.y * inv));

    // ---- gemm2 on registers: Wh2[node] = h . W2 ----
    unsigned long long acc2 = 0ull;
#pragma unroll
    for (int k = 0; k < O1; k++) {
        float xk = __shfl_sync(FULLM, (k & 1) ? hv.y : hv.x, k >> 1);
        fma2(acc2, pack2(xk, xk), sW2[k * 32 + lane]);
    }
    float2 o2 = unpack2(acc2);
    *(float2*)&g_Wh2[(size_t)node * NLAB + 2 * lane] = o2;
    float ps = o2.x * sa2s[2 * lane] + o2.y * sa2s[2 * lane + 1];
    float pd = o2.x * sa2d[2 * lane] + o2.y * sa2d[2 * lane + 1];
#pragma unroll
    for (int o = 16; o; o >>= 1) {
        ps += __shfl_xor_sync(FULLM, ps, o);
        pd += __shfl_xor_sync(FULLM, pd, o);
    }
    if (lane == 0) { g_es2[node] = ps; g_ed2[node] = pd; }
}

// ========== K5: layer-2 aggregate + final softmax + cnt re-zero ==========
__global__ __launch_bounds__(256) void k5_agg2(float* __restrict__ out) {
    int gid = blockIdx.x * blockDim.x + threadIdx.x;
    if (gid < NN) g_cnt[gid] = 0;   // leave cnt zeroed for the next call

    int node = gid >> 5;
    int lane = threadIdx.x & 31;
    if (node >= NN) return;
    const int beg = g_off[node], end = g_off[node + 1];
    const float ed = g_ed2[node];

    float sumP = 0.f;
    float2 acc = make_float2(0.f, 0.f);
    for (int base = beg; base < end; base += 32) {
        int rem = end - base;
        int s_l = (lane < rem) ? g_ssrc[base + lane] : 0;
        int m = rem < 32 ? rem : 32;
        for (int j = 0; j < m; j++) {
            int s = __shfl_sync(FULLM, s_l, j);
            float p = __expf(lrelu_f(g_es2[s] + ed));
            float2 w2 = *(const float2*)&g_Wh2[(size_t)s * NLAB + 2 * lane];
            sumP += p;
            acc.x += p * w2.x;
            acc.y += p * w2.y;
        }
    }
    const float inv = 1.f / (sumP + 1e-10f);
    float o0 = acc.x * inv;
    float o1 = acc.y * inv;

    // head-mean is identity (H2=1); fused softmax over 64 classes
    float m2 = fmaxf(o0, o1);
#pragma unroll
    for (int o = 16; o; o >>= 1) m2 = fmaxf(m2, __shfl_xor_sync(FULLM, m2, o));
    float e0 = __expf(o0 - m2);
    float e1 = __expf(o1 - m2);
    float s2 = e0 + e1;
#pragma unroll
    for (int o = 16; o; o >>= 1) s2 += __shfl_xor_sync(FULLM, s2, o);
    float r = 1.f / s2;
    *(float2*)&out[(size_t)node * NLAB + 2 * lane] = make_float2(e0 * r, e1 * r);
}

// ---------------- launch ----------------
extern "C" void kernel_launch(void* const* d_in, const int* in_sizes, int n_in,
                              void* d_out, int out_size) {
    const float* x    = (const float*)d_in[0];
    const float* W1   = (const float*)d_in[1];
    const float* a1s  = (const float*)d_in[2];
    const float* a1d  = (const float*)d_in[3];
    const float* W2   = (const float*)d_in[4];
    const float* a2s  = (const float*)d_in[5];
    const float* a2d  = (const float*)d_in[6];
    const int*   src  = (const int*)d_in[7];
    const int*   dst  = (const int*)d_in[8];
    float* out = (float*)d_out;

    k1_prep_hist<<<32 + HIST_BLKS, 256>>>(W1, dst);
    k2_gemm1_scan<<<1 + (NN + G1_NB - 1) / G1_NB, 256>>>(x, a1s, a1d);
    k3_scatter<<<HIST_BLKS, 256>>>(src, dst);
    k4_agg1_gemm2<<<(NN + 7) / 8, 256>>>(W2, a2s, a2d);
    k5_agg2<<<(NN * 32 + 255) / 256, 256>>>(out);
}